// round 13
// baseline (speedup 1.0000x reference)
#include <cuda_runtime.h>
#include <cuda_fp16.h>

#define N_NODES  100000
#define N_EDGES  1600000
#define N_GRAPHS 512
#define F        32
#define CAP      64          // max in-degree bucket capacity (P(deg>=64) ~ 1e-18)

// ---------------- scratch (static __device__ globals; zero at load) --------
__device__ __align__(128) int    g_cnt_i[N_NODES];          // fill cursors (re-zeroed by k_agg2)
__device__ __align__(128) int    g_deg8[N_NODES];           // padded (mult-of-8) counts
__device__ __align__(128) int    g_bucket[N_NODES * CAP];   // src lists, 25.6MB
__device__ __align__(128) float  g_dinv[N_NODES];
__device__ __align__(128) float4 g_xs[N_NODES + 1];         // dinv[s]*x[s]; row N_NODES = 0
__device__ __align__(128) __half g_h1[(N_NODES + 1) * F];   // dinv*relu(conv1), fp16 64B rows
__device__ __align__(128) float  g_sums[N_GRAPHS * F];
__device__ __align__(128) float  g_cnt[N_GRAPHS];

// ---------------- K1: bucket fill ------------------------------------------
__global__ void k_fill(const int* __restrict__ ei) {
    int e = blockIdx.x * blockDim.x + threadIdx.x;
    if (e >= N_EDGES) return;
    int s = ei[e];
    int d = ei[N_EDGES + e];
    int r = atomicAdd(&g_cnt_i[d], 1);
    if (r < CAP) g_bucket[d * CAP + r] = s;
}

// ---------------- K2: dinv, pre-scaled x, bucket pad, zero pool accums -----
__global__ void k_prep(const float* __restrict__ x) {
    int i = blockIdx.x * blockDim.x + threadIdx.x;
    if (i < N_NODES) {
        int c = min(g_cnt_i[i], CAP);
        float di = rsqrtf((float)c + 1.0f);
        g_dinv[i] = di;
        float x0 = x[i * 3 + 0], x1 = x[i * 3 + 1], x2 = x[i * 3 + 2];
        g_xs[i] = make_float4(di * x0, di * x1, di * x2, 0.0f);
        int c8 = (c + 7) & ~7;
        g_deg8[i] = c8;
        for (int r = c; r < c8; r++) g_bucket[i * CAP + r] = N_NODES;  // dummy
    }
    if (i < N_GRAPHS * F) g_sums[i] = 0.0f;
    if (i < N_GRAPHS) g_cnt[i] = 0.0f;
}

// ---------------- K3: layer1 — lane-parallel float4 gather -----------------
// conv1[w] = di*(Σ xs[s] + xs[w]); h1 = di*relu(conv1@W1 + b1) stored fp16
__global__ void k_agg1(const float* __restrict__ x,
                       const float* __restrict__ W1,
                       const float* __restrict__ b1) {
    __shared__ float W1s[96];
    int tid = threadIdx.x;
    if (tid < 96) W1s[tid] = W1[tid];
    __syncthreads();
    int w = (blockIdx.x * blockDim.x + tid) >> 5;
    int lane = tid & 31;
    if (w >= N_NODES) return;
    int cnt8 = g_deg8[w];
    float a0 = 0.0f, a1 = 0.0f, a2 = 0.0f;
    for (int j = lane; j < cnt8; j += 32) {        // coalesced bucket reads
        int s = g_bucket[w * CAP + j];
        float4 v = g_xs[s];                        // 16B gather (dummy -> 0)
        a0 += v.x; a1 += v.y; a2 += v.z;
    }
#pragma unroll
    for (int o = 16; o > 0; o >>= 1) {             // warp-reduce 3 partials
        a0 += __shfl_xor_sync(0xffffffffu, a0, o);
        a1 += __shfl_xor_sync(0xffffffffu, a1, o);
        a2 += __shfl_xor_sync(0xffffffffu, a2, o);
    }
    float4 sw = g_xs[w];                           // self loop (warp-uniform)
    float di = g_dinv[w];
    a0 = (a0 + sw.x) * di;
    a1 = (a1 + sw.y) * di;
    a2 = (a2 + sw.z) * di;
    float h = a0 * W1s[lane] + a1 * W1s[32 + lane] + a2 * W1s[64 + lane] + b1[lane];
    g_h1[w * F + lane] = __float2half(di * fmaxf(h, 0.0f));  // fp16, 64B row
}

// ---------------- K4: layer2 — plain-sum gather of fp16 rows ---------------
// agg = di*(Σ h1[s] + h1[w]); out = relu(agg@W2 + b2); pool
__global__ void k_agg2(const float* __restrict__ b2,
                       const float* __restrict__ W2,
                       const int* __restrict__ batch) {
    __shared__ float W2s[F * F];
    int tid = threadIdx.x;
    for (int i = tid; i < F * F; i += blockDim.x) W2s[i] = W2[i];
    __syncthreads();
    int gidx = blockIdx.x * blockDim.x + tid;
    // re-zero fill cursors for the NEXT run (nobody reads g_cnt_i here)
    if (gidx < N_NODES) g_cnt_i[gidx] = 0;

    int w = gidx >> 5;
    int lane = tid & 31;
    if (w >= N_NODES) return;
    int cnt8 = g_deg8[w];
    float acc = __half2float(g_h1[w * F + lane]);  // self loop (pre-scaled)
    const int4* bk4 = reinterpret_cast<const int4*>(&g_bucket[w * CAP]);
    for (int j = 0; j < cnt8; j += 8) {
        int4 q0 = bk4[(j >> 2) + 0];               // 2 broadcast LDG.128 = 8 idx
        int4 q1 = bk4[(j >> 2) + 1];
        float v0 = __half2float(g_h1[q0.x * F + lane]);   // 64B-row gathers:
        float v1 = __half2float(g_h1[q0.y * F + lane]);   // 2 sectors/miss
        float v2 = __half2float(g_h1[q0.z * F + lane]);
        float v3 = __half2float(g_h1[q0.w * F + lane]);
        float v4 = __half2float(g_h1[q1.x * F + lane]);
        float v5 = __half2float(g_h1[q1.y * F + lane]);
        float v6 = __half2float(g_h1[q1.z * F + lane]);
        float v7 = __half2float(g_h1[q1.w * F + lane]);
        acc += ((v0 + v1) + (v2 + v3)) + ((v4 + v5) + (v6 + v7));
    }
    acc *= g_dinv[w];
    // epilogue: o = agg @ W2; h2 = relu(o + b2); pool
    float o = 0.0f;
#pragma unroll
    for (int k = 0; k < F; k++) {
        float ak = __shfl_sync(0xffffffffu, acc, k);
        o = fmaf(ak, W2s[k * F + lane], o);
    }
    float h = fmaxf(o + b2[lane], 0.0f);
    int g = batch[w];
    atomicAdd(&g_sums[g * F + lane], h);
    if (lane == 0) atomicAdd(&g_cnt[g], 1.0f);
}

// ---------------- K5: out = (sums/cnt)@Wl + bl -----------------------------
__global__ void k_out(const float* __restrict__ Wl,
                      const float* __restrict__ bl,
                      float* __restrict__ out) {
    int idx = blockIdx.x * blockDim.x + threadIdx.x;
    if (idx >= N_GRAPHS * 2) return;
    int g = idx >> 1, j = idx & 1;
    float inv = 1.0f / fmaxf(g_cnt[g], 1.0f);
    float acc = 0.0f;
#pragma unroll
    for (int f = 0; f < F; f++) acc += g_sums[g * F + f] * Wl[f * 2 + j];
    out[idx] = acc * inv + bl[j];
}

// ---------------- launch: 5 kernels ----------------------------------------
extern "C" void kernel_launch(void* const* d_in, const int* in_sizes, int n_in,
                              void* d_out, int out_size) {
    const float* x     = (const float*)d_in[0];
    const int*   ei    = (const int*)d_in[1];    // int64 -> int32 by harness
    const int*   batch = (const int*)d_in[2];
    const float* W1    = (const float*)d_in[3];
    const float* b1    = (const float*)d_in[4];
    const float* W2    = (const float*)d_in[5];
    const float* b2    = (const float*)d_in[6];
    const float* Wl    = (const float*)d_in[7];
    const float* bl    = (const float*)d_in[8];
    float*       out   = (float*)d_out;

    const int TB = 256;
    k_fill<<<(N_EDGES + TB - 1) / TB, TB>>>(ei);
    k_prep<<<(N_NODES + TB - 1) / TB, TB>>>(x);
    k_agg1<<<(N_NODES * 32 + TB - 1) / TB, TB>>>(x, W1, b1);
    k_agg2<<<(N_NODES * 32 + TB - 1) / TB, TB>>>(b2, W2, batch);
    k_out <<<(N_GRAPHS * 2 + TB - 1) / TB, TB>>>(Wl, bl, out);
}

// round 14
// speedup vs baseline: 1.0847x; 1.0847x over previous
#include <cuda_runtime.h>

#define N_NODES  100000
#define N_EDGES  1600000
#define N_GRAPHS 512
#define F        32
#define CAP      64          // max in-degree bucket capacity (P(deg>=64) ~ 1e-18)

// ---------------- scratch (static __device__ globals; zero at load) --------
__device__ __align__(128) int    g_cnt_i[N_NODES];          // fill cursors (re-zeroed by k_agg2)
__device__ __align__(128) int    g_deg4[N_NODES];           // padded (mult-of-4) counts
__device__ __align__(128) int    g_bucket[N_NODES * CAP];   // src lists, 25.6MB
__device__ __align__(128) float  g_dinv[N_NODES];
__device__ __align__(128) float4 g_xs[N_NODES + 1];         // dinv[s]*x[s]; row N_NODES = 0
__device__ __align__(128) float  g_h1[(N_NODES + 1) * F];   // dinv*relu(conv1); dummy row = 0
__device__ __align__(128) float  g_sums[N_GRAPHS * F];
__device__ __align__(128) float  g_cnt[N_GRAPHS];

// ---------------- K1: bucket fill ------------------------------------------
__global__ void k_fill(const int* __restrict__ ei) {
    int e = blockIdx.x * blockDim.x + threadIdx.x;
    if (e >= N_EDGES) return;
    int s = ei[e];
    int d = ei[N_EDGES + e];
    int r = atomicAdd(&g_cnt_i[d], 1);
    if (r < CAP) g_bucket[d * CAP + r] = s;
}

// ---------------- K2: dinv, pre-scaled x, bucket pad, zero pool accums -----
__global__ void k_prep(const float* __restrict__ x) {
    int i = blockIdx.x * blockDim.x + threadIdx.x;
    if (i < N_NODES) {
        int c = min(g_cnt_i[i], CAP);
        float di = rsqrtf((float)c + 1.0f);
        g_dinv[i] = di;
        float x0 = x[i * 3 + 0], x1 = x[i * 3 + 1], x2 = x[i * 3 + 2];
        g_xs[i] = make_float4(di * x0, di * x1, di * x2, 0.0f);
        int c4 = (c + 3) & ~3;
        g_deg4[i] = c4;
        for (int r = c; r < c4; r++) g_bucket[i * CAP + r] = N_NODES;  // dummy
    }
    if (i < N_GRAPHS * F) g_sums[i] = 0.0f;
    if (i < N_GRAPHS) g_cnt[i] = 0.0f;
}

// ---------------- K3: layer1 — lane-parallel float4 gather -----------------
// conv1[w] = di*(Σ xs[s] + xs[w]); h1 = di*relu(conv1@W1 + b1)
__global__ void k_agg1(const float* __restrict__ x,
                       const float* __restrict__ W1,
                       const float* __restrict__ b1) {
    __shared__ float W1s[96];
    int tid = threadIdx.x;
    if (tid < 96) W1s[tid] = W1[tid];
    __syncthreads();
    int w = (blockIdx.x * blockDim.x + tid) >> 5;
    int lane = tid & 31;
    if (w >= N_NODES) return;
    int cnt4 = g_deg4[w];
    float a0 = 0.0f, a1 = 0.0f, a2 = 0.0f;
    for (int j = lane; j < cnt4; j += 32) {        // coalesced bucket reads
        int s = g_bucket[w * CAP + j];
        float4 v = g_xs[s];                        // 16B gather (dummy -> 0)
        a0 += v.x; a1 += v.y; a2 += v.z;
    }
#pragma unroll
    for (int o = 16; o > 0; o >>= 1) {             // warp-reduce 3 partials
        a0 += __shfl_xor_sync(0xffffffffu, a0, o);
        a1 += __shfl_xor_sync(0xffffffffu, a1, o);
        a2 += __shfl_xor_sync(0xffffffffu, a2, o);
    }
    float4 sw = g_xs[w];                           // self loop (warp-uniform)
    float di = g_dinv[w];
    a0 = (a0 + sw.x) * di;
    a1 = (a1 + sw.y) * di;
    a2 = (a2 + sw.z) * di;
    float h = a0 * W1s[lane] + a1 * W1s[32 + lane] + a2 * W1s[64 + lane] + b1[lane];
    g_h1[w * F + lane] = di * fmaxf(h, 0.0f);      // pre-scaled for layer 2
}

// ---------------- K4: layer2 — 4 edges per LDG.128 full-row gather ---------
// lane = edge-group(g=lane>>3) x feature-quad(q=lane&7); row = 8 float4s.
__global__ void k_agg2(const float* __restrict__ b2,
                       const float* __restrict__ W2,
                       const int* __restrict__ batch) {
    __shared__ float W2s[F * F];
    int tid = threadIdx.x;
    for (int i = tid; i < F * F; i += blockDim.x) W2s[i] = W2[i];
    __syncthreads();
    int gidx = blockIdx.x * blockDim.x + tid;
    // re-zero fill cursors for the NEXT run (nobody reads g_cnt_i here)
    if (gidx < N_NODES) g_cnt_i[gidx] = 0;

    int w = gidx >> 5;
    int lane = tid & 31;
    if (w >= N_NODES) return;
    int grp = lane >> 3;                           // edge group 0..3
    int q   = lane & 7;                            // feature quad 0..7
    int cnt4 = g_deg4[w];
    const float4* h1r = reinterpret_cast<const float4*>(g_h1);  // 8 quads/row
    const int* bk = &g_bucket[w * CAP];
    float4 acc = make_float4(0.0f, 0.0f, 0.0f, 0.0f);
    for (int j = 0; j < cnt4; j += 4) {
        int s = bk[j + grp];                       // 16B window: 1 wavefront
        float4 v = h1r[s * 8 + q];                 // LDG.128: 4 rows/warp
        acc.x += v.x; acc.y += v.y; acc.z += v.z; acc.w += v.w;
    }
    // reduce across the 4 edge groups (features stay in place)
#pragma unroll
    for (int o = 8; o <= 16; o <<= 1) {
        acc.x += __shfl_xor_sync(0xffffffffu, acc.x, o);
        acc.y += __shfl_xor_sync(0xffffffffu, acc.y, o);
        acc.z += __shfl_xor_sync(0xffffffffu, acc.z, o);
        acc.w += __shfl_xor_sync(0xffffffffu, acc.w, o);
    }
    float4 sv = h1r[w * 8 + q];                    // self loop (replicated x4)
    float di = g_dinv[w];
    acc.x = (acc.x + sv.x) * di;
    acc.y = (acc.y + sv.y) * di;
    acc.z = (acc.z + sv.z) * di;
    acc.w = (acc.w + sv.w) * di;
    // epilogue: o = agg @ W2  (a_k lives in lane k>>2, component k&3)
    float o = 0.0f;
#pragma unroll
    for (int k = 0; k < F; k++) {
        float comp = (k & 3) == 0 ? acc.x : (k & 3) == 1 ? acc.y
                   : (k & 3) == 2 ? acc.z : acc.w;
        float ak = __shfl_sync(0xffffffffu, comp, k >> 2);
        o = fmaf(ak, W2s[k * F + lane], o);
    }
    float h = fmaxf(o + b2[lane], 0.0f);
    int g = batch[w];
    atomicAdd(&g_sums[g * F + lane], h);
    if (lane == 0) atomicAdd(&g_cnt[g], 1.0f);
}

// ---------------- K5: out = (sums/cnt)@Wl + bl -----------------------------
__global__ void k_out(const float* __restrict__ Wl,
                      const float* __restrict__ bl,
                      float* __restrict__ out) {
    int idx = blockIdx.x * blockDim.x + threadIdx.x;
    if (idx >= N_GRAPHS * 2) return;
    int g = idx >> 1, j = idx & 1;
    float inv = 1.0f / fmaxf(g_cnt[g], 1.0f);
    float acc = 0.0f;
#pragma unroll
    for (int f = 0; f < F; f++) acc += g_sums[g * F + f] * Wl[f * 2 + j];
    out[idx] = acc * inv + bl[j];
}

// ---------------- launch: 5 kernels ----------------------------------------
extern "C" void kernel_launch(void* const* d_in, const int* in_sizes, int n_in,
                              void* d_out, int out_size) {
    const float* x     = (const float*)d_in[0];
    const int*   ei    = (const int*)d_in[1];    // int64 -> int32 by harness
    const int*   batch = (const int*)d_in[2];
    const float* W1    = (const float*)d_in[3];
    const float* b1    = (const float*)d_in[4];
    const float* W2    = (const float*)d_in[5];
    const float* b2    = (const float*)d_in[6];
    const float* Wl    = (const float*)d_in[7];
    const float* bl    = (const float*)d_in[8];
    float*       out   = (float*)d_out;

    const int TB = 256;
    k_fill<<<(N_EDGES + TB - 1) / TB, TB>>>(ei);
    k_prep<<<(N_NODES + TB - 1) / TB, TB>>>(x);
    k_agg1<<<(N_NODES * 32 + TB - 1) / TB, TB>>>(x, W1, b1);
    k_agg2<<<(N_NODES * 32 + TB - 1) / TB, TB>>>(b2, W2, batch);
    k_out <<<(N_GRAPHS * 2 + TB - 1) / TB, TB>>>(Wl, bl, out);
}

// round 15
// speedup vs baseline: 1.2407x; 1.1438x over previous
#include <cuda_runtime.h>

#define N_NODES  100000
#define N_EDGES  1600000
#define N_GRAPHS 512
#define F        32
#define CAP      64          // max in-degree bucket capacity (P(deg>=64) ~ 1e-18)

// ---------------- scratch (static __device__ globals; zero at load) --------
__device__ __align__(128) int    g_cnt_i[N_NODES];          // fill cursors (re-zeroed by k_agg2)
__device__ __align__(128) int    g_deg8[N_NODES];           // padded (mult-of-8) counts
__device__ __align__(128) int    g_bucket[N_NODES * CAP];   // src lists, 25.6MB
__device__ __align__(128) float  g_dinv[N_NODES];
__device__ __align__(128) float4 g_xs[N_NODES + 1];         // dinv[s]*x[s]; row N_NODES = 0
__device__ __align__(128) float  g_h1[(N_NODES + 1) * F];   // dinv*relu(conv1); dummy row = 0
__device__ __align__(128) float  g_sums[N_GRAPHS * F];
__device__ __align__(128) float  g_cnt[N_GRAPHS];

// ---------------- K1: bucket fill ------------------------------------------
__global__ void k_fill(const int* __restrict__ ei) {
    int e = blockIdx.x * blockDim.x + threadIdx.x;
    if (e >= N_EDGES) return;
    int s = ei[e];
    int d = ei[N_EDGES + e];
    int r = atomicAdd(&g_cnt_i[d], 1);
    if (r < CAP) g_bucket[d * CAP + r] = s;
}

// ---------------- K2: dinv, pre-scaled x, bucket pad, zero pool accums -----
__global__ void k_prep(const float* __restrict__ x) {
    int i = blockIdx.x * blockDim.x + threadIdx.x;
    if (i < N_NODES) {
        int c = min(g_cnt_i[i], CAP);
        float di = rsqrtf((float)c + 1.0f);
        g_dinv[i] = di;
        float x0 = x[i * 3 + 0], x1 = x[i * 3 + 1], x2 = x[i * 3 + 2];
        g_xs[i] = make_float4(di * x0, di * x1, di * x2, 0.0f);
        int c8 = (c + 7) & ~7;
        g_deg8[i] = c8;
        for (int r = c; r < c8; r++) g_bucket[i * CAP + r] = N_NODES;  // dummy
    }
    if (i < N_GRAPHS * F) g_sums[i] = 0.0f;
    if (i < N_GRAPHS) g_cnt[i] = 0.0f;
}

// ---------------- K3: layer1 — lane-parallel float4 gather -----------------
// conv1[w] = di*(Σ xs[s] + xs[w]); h1 = di*relu(conv1@W1 + b1)
__global__ void k_agg1(const float* __restrict__ x,
                       const float* __restrict__ W1,
                       const float* __restrict__ b1) {
    __shared__ float W1s[96];
    int tid = threadIdx.x;
    if (tid < 96) W1s[tid] = W1[tid];
    __syncthreads();
    int w = (blockIdx.x * blockDim.x + tid) >> 5;
    int lane = tid & 31;
    if (w >= N_NODES) return;
    int cnt8 = g_deg8[w];
    float a0 = 0.0f, a1 = 0.0f, a2 = 0.0f;
    for (int j = lane; j < cnt8; j += 32) {        // coalesced bucket reads
        int s = g_bucket[w * CAP + j];
        float4 v = g_xs[s];                        // 16B gather (dummy -> 0)
        a0 += v.x; a1 += v.y; a2 += v.z;
    }
#pragma unroll
    for (int o = 16; o > 0; o >>= 1) {             // warp-reduce 3 partials
        a0 += __shfl_xor_sync(0xffffffffu, a0, o);
        a1 += __shfl_xor_sync(0xffffffffu, a1, o);
        a2 += __shfl_xor_sync(0xffffffffu, a2, o);
    }
    float4 sw = g_xs[w];                           // self loop (warp-uniform)
    float di = g_dinv[w];
    a0 = (a0 + sw.x) * di;
    a1 = (a1 + sw.y) * di;
    a2 = (a2 + sw.z) * di;
    float h = a0 * W1s[lane] + a1 * W1s[32 + lane] + a2 * W1s[64 + lane] + b1[lane];
    g_h1[w * F + lane] = di * fmaxf(h, 0.0f);      // pre-scaled for layer 2
}

// ---------------- K4: layer2 — unroll-2 float4-row gather + smem pool ------
// lane = edge-group(grp=lane>>3) x feature-quad(q=lane&7); row = 8 float4s.
// Grid is EXACTLY 12500 blocks x 8 warps = 100000 nodes (no tail; syncthreads safe)
__global__ void k_agg2(const float* __restrict__ b2,
                       const float* __restrict__ W2,
                       const int* __restrict__ batch) {
    __shared__ float W2s[F * F];
    __shared__ float s_h[8][F];
    __shared__ int   s_g[8];
    int tid = threadIdx.x;
    for (int i = tid; i < F * F; i += blockDim.x) W2s[i] = W2[i];
    __syncthreads();
    int gidx = blockIdx.x * blockDim.x + tid;
    // re-zero fill cursors for the NEXT run (nobody reads g_cnt_i here)
    if (gidx < N_NODES) g_cnt_i[gidx] = 0;

    int w = gidx >> 5;                             // always < N_NODES (exact grid)
    int lane = tid & 31;
    int warp = tid >> 5;
    int grp = lane >> 3;                           // edge group 0..3
    int q   = lane & 7;                            // feature quad 0..7
    int cnt8 = g_deg8[w];
    const float4* h1r = reinterpret_cast<const float4*>(g_h1);  // 8 quads/row
    const int* bk = &g_bucket[w * CAP];
    float4 acc0 = make_float4(0.0f, 0.0f, 0.0f, 0.0f);
    float4 acc1 = make_float4(0.0f, 0.0f, 0.0f, 0.0f);
    for (int j = 0; j < cnt8; j += 8) {            // 2 gathers in flight
        int s0 = bk[j + grp];
        int s1 = bk[j + 4 + grp];
        float4 v0 = h1r[s0 * 8 + q];
        float4 v1 = h1r[s1 * 8 + q];
        acc0.x += v0.x; acc0.y += v0.y; acc0.z += v0.z; acc0.w += v0.w;
        acc1.x += v1.x; acc1.y += v1.y; acc1.z += v1.z; acc1.w += v1.w;
    }
    float4 acc = make_float4(acc0.x + acc1.x, acc0.y + acc1.y,
                             acc0.z + acc1.z, acc0.w + acc1.w);
    // reduce across the 4 edge groups (features stay in place)
#pragma unroll
    for (int o = 8; o <= 16; o <<= 1) {
        acc.x += __shfl_xor_sync(0xffffffffu, acc.x, o);
        acc.y += __shfl_xor_sync(0xffffffffu, acc.y, o);
        acc.z += __shfl_xor_sync(0xffffffffu, acc.z, o);
        acc.w += __shfl_xor_sync(0xffffffffu, acc.w, o);
    }
    float4 sv = h1r[w * 8 + q];                    // self loop (replicated x4)
    float di = g_dinv[w];
    acc.x = (acc.x + sv.x) * di;
    acc.y = (acc.y + sv.y) * di;
    acc.z = (acc.z + sv.z) * di;
    acc.w = (acc.w + sv.w) * di;
    // epilogue: o = agg @ W2  (a_k lives in lane k>>2, component k&3)
    float o = 0.0f;
#pragma unroll
    for (int k = 0; k < F; k++) {
        float comp = (k & 3) == 0 ? acc.x : (k & 3) == 1 ? acc.y
                   : (k & 3) == 2 ? acc.z : acc.w;
        float ak = __shfl_sync(0xffffffffu, comp, k >> 2);
        o = fmaf(ak, W2s[k * F + lane], o);
    }
    float h = fmaxf(o + b2[lane], 0.0f);
    int g = batch[w];
    // ---- pooled atomics: one atomic row per block when graph is uniform ----
    s_h[warp][lane] = h;
    if (lane == 0) s_g[warp] = g;
    __syncthreads();
    bool eq = (lane < 8) ? (s_g[lane] == s_g[0]) : true;
    bool uni = __all_sync(0xffffffffu, eq);
    if (uni) {
        if (warp == 0) {
            float t = 0.0f;
#pragma unroll
            for (int r = 0; r < 8; r++) t += s_h[r][lane];
            atomicAdd(&g_sums[s_g[0] * F + lane], t);
            if (lane == 0) atomicAdd(&g_cnt[s_g[0]], 8.0f);
        }
    } else {
        atomicAdd(&g_sums[g * F + lane], h);
        if (lane == 0) atomicAdd(&g_cnt[g], 1.0f);
    }
}

// ---------------- K5: out = (sums/cnt)@Wl + bl -----------------------------
__global__ void k_out(const float* __restrict__ Wl,
                      const float* __restrict__ bl,
                      float* __restrict__ out) {
    int idx = blockIdx.x * blockDim.x + threadIdx.x;
    if (idx >= N_GRAPHS * 2) return;
    int g = idx >> 1, j = idx & 1;
    float inv = 1.0f / fmaxf(g_cnt[g], 1.0f);
    float acc = 0.0f;
#pragma unroll
    for (int f = 0; f < F; f++) acc += g_sums[g * F + f] * Wl[f * 2 + j];
    out[idx] = acc * inv + bl[j];
}

// ---------------- launch: 5 kernels ----------------------------------------
extern "C" void kernel_launch(void* const* d_in, const int* in_sizes, int n_in,
                              void* d_out, int out_size) {
    const float* x     = (const float*)d_in[0];
    const int*   ei    = (const int*)d_in[1];    // int64 -> int32 by harness
    const int*   batch = (const int*)d_in[2];
    const float* W1    = (const float*)d_in[3];
    const float* b1    = (const float*)d_in[4];
    const float* W2    = (const float*)d_in[5];
    const float* b2    = (const float*)d_in[6];
    const float* Wl    = (const float*)d_in[7];
    const float* bl    = (const float*)d_in[8];
    float*       out   = (float*)d_out;

    const int TB = 256;
    k_fill<<<(N_EDGES + TB - 1) / TB, TB>>>(ei);
    k_prep<<<(N_NODES + TB - 1) / TB, TB>>>(x);
    k_agg1<<<(N_NODES * 32 + TB - 1) / TB, TB>>>(x, W1, b1);
    k_agg2<<<N_NODES / 8, TB>>>(b2, W2, batch);     // exact: 12500 blocks
    k_out <<<(N_GRAPHS * 2 + TB - 1) / TB, TB>>>(Wl, bl, out);
}